// round 16
// baseline (speedup 1.0000x reference)
#include <cuda_runtime.h>
#include <math.h>
#include <stdint.h>

#define Hh   12
#define Nn   768
#define C1d  384
#define C2d  128
#define PROJ_DIM 1152
#define FA_DIM   2112

#define SCALAR_W 0.14433756729740643f
#define POINT_W  0.13608276348795434f
#define W2D      0.5773502691896258f

// ---------------- scratch ----------------
__device__ float d_proj[Nn * PROJ_DIM];
__device__ float d_qcat[Nn * 384];
__device__ float d_kT[Hh * 29 * Nn];
__device__ float d_vcat[Nn * 480];
__device__ float d_lgsp[Nn * Hh * Nn];
__device__ float d_attn[Hh * Nn * Nn];
__device__ float d_rpg[Nn * 288];
__device__ float d_fa[Nn * FA_DIM];
__device__ float d_part[4 * Nn * 384];

__device__ __forceinline__ unsigned smem_u32(const void* p) {
    unsigned a;
    asm("{ .reg .u64 t; cvta.to.shared.u64 t, %1; cvt.u32.u64 %0, t; }" : "=r"(a) : "l"(p));
    return a;
}
__device__ __forceinline__ void cp4(unsigned dst, const float* src) {
    asm volatile("cp.async.ca.shared.global [%0], [%1], 4;" :: "r"(dst), "l"(src));
}

// ---------------- K1: proj GEMM fp32, cp.async double buffer, inline weight concat ----------------
__global__ __launch_bounds__(256) void gemm_proj_kernel(
        const float* __restrict__ X,
        const float* __restrict__ wqs, const float* __restrict__ wkvs,
        const float* __restrict__ wqp, const float* __restrict__ wkvp,
        const float* __restrict__ bqs, const float* __restrict__ bkvs,
        const float* __restrict__ bqp, const float* __restrict__ bkvp) {
    __shared__ float xsT[2][16][68];
    __shared__ float wsT[2][16][68];
    const int m0 = blockIdx.y * 64, o0 = blockIdx.x * 64;
    const int tx = threadIdx.x;
    const int tm = (tx & 15) * 4;
    const int to = (tx >> 4) * 4;
    const unsigned xb = smem_u32(&xsT[0][0][0]);
    const unsigned wb = smem_u32(&wsT[0][0][0]);
    float acc[4][4] = {};

    auto issue = [&](int buf, int k0) {
#pragma unroll
        for (int t = 0; t < 4; t++) {
            int idx = tx + 256 * t;
            int r = idx >> 4, c = idx & 15;
            cp4(xb + (unsigned)(buf * 1088 + c * 68 + r) * 4u,
                X + (size_t)(m0 + r) * C1d + k0 + c);
            int o = o0 + r;
            const float* wrow;
            if (o < 192)      wrow = wqs  + (size_t)o * C1d;
            else if (o < 576) wrow = wkvs + (size_t)(o - 192) * C1d;
            else if (o < 720) wrow = wqp  + (size_t)(o - 576) * C1d;
            else              wrow = wkvp + (size_t)(o - 720) * C1d;
            cp4(wb + (unsigned)(buf * 1088 + c * 68 + r) * 4u, wrow + k0 + c);
        }
        asm volatile("cp.async.commit_group;");
    };

    issue(0, 0);
    const int NK = C1d / 16;
    for (int kk = 0; kk < NK; kk++) {
        const int buf = kk & 1;
        if (kk + 1 < NK) {
            issue(buf ^ 1, (kk + 1) * 16);
            asm volatile("cp.async.wait_group 1;");
        } else {
            asm volatile("cp.async.wait_group 0;");
        }
        __syncthreads();
#pragma unroll
        for (int k = 0; k < 16; k++) {
            float4 av = *(const float4*)&xsT[buf][k][tm];
            float4 bv = *(const float4*)&wsT[buf][k][to];
            float a[4] = {av.x, av.y, av.z, av.w};
            float b[4] = {bv.x, bv.y, bv.z, bv.w};
#pragma unroll
            for (int i = 0; i < 4; i++)
#pragma unroll
                for (int j = 0; j < 4; j++) acc[i][j] += a[i] * b[j];
        }
        __syncthreads();
    }
#pragma unroll
    for (int i = 0; i < 4; i++)
#pragma unroll
        for (int j = 0; j < 4; j++) {
            int o = o0 + to + j;
            float bv;
            if (o < 192)      bv = bqs[o];
            else if (o < 576) bv = bkvs[o - 192];
            else if (o < 720) bv = bqp[o - 576];
            else              bv = bkvp[o - 720];
            d_proj[(size_t)(m0 + tm + i) * PROJ_DIM + o] = acc[i][j] + bv;
        }
}

// ---------------- out-GEMM fp32, cp.async double buffer, K-split on blockIdx.z ----------------
__global__ __launch_bounds__(256) void gemm_out_kernel(const float* __restrict__ Wo) {
    __shared__ float xsT[2][16][68];
    __shared__ float wsT[2][16][68];
    const int z  = blockIdx.z;
    const float* X = d_fa + z * 528;
    const float* W = Wo + z * 528;
    float* C = d_part + (size_t)z * (Nn * 384);
    const int m0 = blockIdx.y * 64, o0 = blockIdx.x * 64;
    const int tx = threadIdx.x;
    const int tm = (tx & 15) * 4;
    const int to = (tx >> 4) * 4;
    const unsigned xb = smem_u32(&xsT[0][0][0]);
    const unsigned wb = smem_u32(&wsT[0][0][0]);
    float acc[4][4] = {};

    auto issue = [&](int buf, int k0) {
#pragma unroll
        for (int t = 0; t < 4; t++) {
            int idx = tx + 256 * t;
            int r = idx >> 4, c = idx & 15;
            cp4(xb + (unsigned)(buf * 1088 + c * 68 + r) * 4u,
                X + (size_t)(m0 + r) * FA_DIM + k0 + c);
            cp4(wb + (unsigned)(buf * 1088 + c * 68 + r) * 4u,
                W + (size_t)(o0 + r) * FA_DIM + k0 + c);
        }
        asm volatile("cp.async.commit_group;");
    };

    issue(0, 0);
    const int NK = 528 / 16;
    for (int kk = 0; kk < NK; kk++) {
        const int buf = kk & 1;
        if (kk + 1 < NK) {
            issue(buf ^ 1, (kk + 1) * 16);
            asm volatile("cp.async.wait_group 1;");
        } else {
            asm volatile("cp.async.wait_group 0;");
        }
        __syncthreads();
#pragma unroll
        for (int k = 0; k < 16; k++) {
            float4 av = *(const float4*)&xsT[buf][k][tm];
            float4 bv = *(const float4*)&wsT[buf][k][to];
            float a[4] = {av.x, av.y, av.z, av.w};
            float b[4] = {bv.x, bv.y, bv.z, bv.w};
#pragma unroll
            for (int i = 0; i < 4; i++)
#pragma unroll
                for (int j = 0; j < 4; j++) acc[i][j] += a[i] * b[j];
        }
        __syncthreads();
    }
#pragma unroll
    for (int i = 0; i < 4; i++)
#pragma unroll
        for (int j = 0; j < 4; j++)
            C[(size_t)(m0 + tm + i) * 384 + o0 + to + j] = acc[i][j];
}

// ---------------- K2: rotations / frames / norms / packed q ----------------
__global__ void rot_kernel(const float* __restrict__ rot, const float* __restrict__ trans,
                           const float* __restrict__ tpw, const float* __restrict__ b_a2) {
    const int n = blockIdx.x;
    const int tid = threadIdx.x;  // 192
    __shared__ float R[9], t3[3], qn_s[Hh], kn_s[Hh], pwb_s[Hh];
    const float* pr = d_proj + (size_t)n * PROJ_DIM;
    if (tid < 9)  R[tid] = rot[n * 9 + tid];
    if (tid < 3)  t3[tid] = trans[n * 3 + tid];
    if (tid < Hh) {
        qn_s[tid] = 0.f; kn_s[tid] = 0.f;
        float x = tpw[tid];
        float sp = (x > 20.f) ? x : log1pf(__expf(x));
        pwb_s[tid] = -0.5f * sp * POINT_W;
    }
    __syncthreads();

    { int h = tid >> 4, f = tid & 15;
      d_qcat[n * 384 + h * 32 + f] = SCALAR_W * pr[tid]; }
    for (int o = tid; o < 384; o += 192) {
        int h = o >> 5, d = o & 31;
        float v = pr[192 + o];
        if (d < 16) d_kT[(size_t)(h * 29 + d) * Nn + n] = v;
        else        d_vcat[(size_t)n * 480 + h * 16 + (d - 16)] = v;
    }
    if (tid < 48) {
        int m = tid;
        float p0 = pr[576 + 0 * 48 + m];
        float p1 = pr[576 + 1 * 48 + m];
        float p2 = pr[576 + 2 * 48 + m];
        float g0 = R[0] * p0 + R[1] * p1 + R[2] * p2 + t3[0];
        float g1 = R[3] * p0 + R[4] * p1 + R[5] * p2 + t3[1];
        float g2 = R[6] * p0 + R[7] * p1 + R[8] * p2 + t3[2];
        int h = m >> 2, p = m & 3;
        float s = -2.f * pwb_s[h];
        int base = n * 384 + h * 32 + 16 + p * 3;
        d_qcat[base + 0] = s * g0; d_qcat[base + 1] = s * g1; d_qcat[base + 2] = s * g2;
        atomicAdd(&qn_s[h], g0 * g0 + g1 * g1 + g2 * g2);
    } else {
        int m = tid - 48;
        float p0 = pr[720 + 0 * 144 + m];
        float p1 = pr[720 + 1 * 144 + m];
        float p2 = pr[720 + 2 * 144 + m];
        float g0 = R[0] * p0 + R[1] * p1 + R[2] * p2 + t3[0];
        float g1 = R[3] * p0 + R[4] * p1 + R[5] * p2 + t3[1];
        float g2 = R[6] * p0 + R[7] * p1 + R[8] * p2 + t3[2];
        int h = m / 12, pp = m % 12;
        if (pp < 4) {
            int fb = h * 29 + 16 + pp * 3;
            d_kT[(size_t)(fb + 0) * Nn + n] = g0;
            d_kT[(size_t)(fb + 1) * Nn + n] = g1;
            d_kT[(size_t)(fb + 2) * Nn + n] = g2;
            atomicAdd(&kn_s[h], g0 * g0 + g1 * g1 + g2 * g2);
        } else {
            int base = n * 480 + 192 + h * 24 + (pp - 4) * 3;
            d_vcat[base + 0] = g0; d_vcat[base + 1] = g1; d_vcat[base + 2] = g2;
        }
    }
    __syncthreads();
    if (tid < Hh) {
        int qb = n * 384 + tid * 32;
        d_qcat[qb + 28] = pwb_s[tid];
        d_qcat[qb + 29] = pwb_s[tid] * qn_s[tid] + W2D * b_a2[tid];
        d_qcat[qb + 30] = 0.f;
        d_qcat[qb + 31] = 0.f;
        d_kT[(size_t)(tid * 29 + 28) * Nn + n] = kn_s[tid];
    }
}

// ---------------- K3: scalar/point logits, K=29 GEMM, 8x8 register tile ----------------
__global__ __launch_bounds__(128) void lgsp_kernel(const float* __restrict__ mask) {
    __shared__ float q_s[64][36];
    __shared__ float kt_s[29][132];
    __shared__ float mj_s[128];
    const int jt = blockIdx.x * 128;
    const int it = blockIdx.y * 64;
    const int h  = blockIdx.z;
    const int tid = threadIdx.x;

    for (int k = tid; k < 512; k += 128) {
        int r = k >> 3, c4 = k & 7;
        *(((float4*)&q_s[r][0]) + c4) =
            *(((const float4*)(d_qcat + (size_t)(it + r) * 384 + h * 32)) + c4);
    }
    for (int k = tid; k < 928; k += 128) {
        int f = k >> 5, c4 = k & 31;
        *(((float4*)&kt_s[f][0]) + c4) =
            *(((const float4*)(d_kT + (size_t)(h * 29 + f) * Nn + jt)) + c4);
    }
    if (tid < 128) mj_s[tid] = mask[jt + tid];
    __syncthreads();

    const int tj = tid & 15, ti = tid >> 4;
    float acc[8][8] = {};
#pragma unroll
    for (int f = 0; f < 29; f++) {
        float a[8];
        float4 b0 = *((const float4*)&kt_s[f][tj * 8]);
        float4 b1 = *((const float4*)&kt_s[f][tj * 8 + 4]);
        float b[8] = {b0.x, b0.y, b0.z, b0.w, b1.x, b1.y, b1.z, b1.w};
#pragma unroll
        for (int r = 0; r < 8; r++) a[r] = q_s[ti * 8 + r][f];
#pragma unroll
        for (int r = 0; r < 8; r++)
#pragma unroll
            for (int c = 0; c < 8; c++) acc[r][c] += a[r] * b[c];
    }
#pragma unroll
    for (int r = 0; r < 8; r++) {
        const int ii = it + ti * 8 + r;
        const float mi = mask[ii];
        const float cih = q_s[ti * 8 + r][29];
        float4* orow = (float4*)(d_lgsp + ((size_t)ii * Hh + h) * Nn + jt + tj * 8);
        float4 o0, o1;
        o0.x = acc[r][0] + cih - 100000.f * (1.f - mi * mj_s[tj * 8 + 0]);
        o0.y = acc[r][1] + cih - 100000.f * (1.f - mi * mj_s[tj * 8 + 1]);
        o0.z = acc[r][2] + cih - 100000.f * (1.f - mi * mj_s[tj * 8 + 2]);
        o0.w = acc[r][3] + cih - 100000.f * (1.f - mi * mj_s[tj * 8 + 3]);
        o1.x = acc[r][4] + cih - 100000.f * (1.f - mi * mj_s[tj * 8 + 4]);
        o1.y = acc[r][5] + cih - 100000.f * (1.f - mi * mj_s[tj * 8 + 5]);
        o1.z = acc[r][6] + cih - 100000.f * (1.f - mi * mj_s[tj * 8 + 6]);
        o1.w = acc[r][7] + cih - 100000.f * (1.f - mi * mj_s[tj * 8 + 7]);
        orow[0] = o0; orow[1] = o1;
    }
}

// ---------------- K4: fused attn — pipelined A; phase C triple-buffer, 1 barrier/chunk ----------------
// 768 blocks, 256 threads, dyn smem 73728 B, 3 blocks/SM
// smem floats (aliased by phase):
//   A: stageA [0,12288)   ws4 [12288,13872)  red [13872,13968)
//   B: att_s  [0,12288)   red [13872,13968)      (att_s: [j][16], h<6 at 0-5, h>=6 at 8-13)
//   C: att_s  [0,12288)   bufC 3x2048 [12288,18432); redc [0,6144) after loop
__global__ void __launch_bounds__(256, 3) attn_fused_kernel(const float* __restrict__ in2d,
                                                            const float* __restrict__ w_a2) {
    extern __shared__ float sm[];
    float4* ws4 = (float4*)(sm + 12288);
    float* red  = sm + 13872;
    float* att_s = sm;

    const int i = blockIdx.x;
    const int tid = threadIdx.x;
    const int wid = tid >> 5, lane = tid & 31;

    const float4* w4g = (const float4*)w_a2;
    for (int k = tid; k < 384; k += 256)
        ws4[(k >> 5) * 33 + (k & 31)] = w4g[k];

    const float4* in4 = (const float4*)in2d + (size_t)i * Nn * 32;
    const unsigned stage_base = smem_u32(sm);

    // ---- phase A: a2d GEMM, 16 chunks of 8 cols, cp.async double buffer ----
    float acc[12][3] = {};
    {
#pragma unroll
        for (int t = 0; t < 6; t++) {
            int k = tid + 256 * t;
            int j = k >> 1, c2 = k & 1;
            const float4* src = in4 + (size_t)j * 32 + c2;
            asm volatile("cp.async.cg.shared.global [%0], [%1], 16;"
                         :: "r"(stage_base + (unsigned)k * 16), "l"(src));
        }
        asm volatile("cp.async.commit_group;");

        for (int ch = 0; ch < 16; ch++) {
            const int buf = ch & 1;
            if (ch + 1 < 16) {
                const unsigned dst0 = stage_base + (unsigned)((buf ^ 1) * 6144) * 4u;
#pragma unroll
                for (int t = 0; t < 6; t++) {
                    int k = tid + 256 * t;
                    int j = k >> 1, c2 = k & 1;
                    const float4* src = in4 + (size_t)j * 32 + (ch + 1) * 2 + c2;
                    asm volatile("cp.async.cg.shared.global [%0], [%1], 16;"
                                 :: "r"(dst0 + (unsigned)k * 16), "l"(src));
                }
                asm volatile("cp.async.commit_group;");
                asm volatile("cp.async.wait_group 1;");
            } else {
                asm volatile("cp.async.wait_group 0;");
            }
            __syncthreads();
            const float4* xsb = (const float4*)(sm + buf * 6144);
#pragma unroll
            for (int c4 = 0; c4 < 2; c4++) {
                float4 xv[3];
#pragma unroll
                for (int u = 0; u < 3; u++) xv[u] = xsb[(tid + 256 * u) * 2 + c4];
#pragma unroll
                for (int h = 0; h < 12; h++) {
                    float4 wv = ws4[h * 33 + ch * 2 + c4];
#pragma unroll
                    for (int u = 0; u < 3; u++)
                        acc[h][u] += xv[u].x * wv.x + xv[u].y * wv.y
                                   + xv[u].z * wv.z + xv[u].w * wv.w;
                }
            }
            __syncthreads();
        }
    }

    // ---- phase B: + lgsp, softmax (register-resident) ----
    const float* lgp = d_lgsp + (size_t)i * Hh * Nn;
#pragma unroll
    for (int h = 0; h < 12; h++) {
        float mx = -1e30f;
#pragma unroll
        for (int u = 0; u < 3; u++) {
            float L = acc[h][u] * W2D + lgp[h * Nn + tid + 256 * u];
            acc[h][u] = L;
            mx = fmaxf(mx, L);
        }
#pragma unroll
        for (int off = 16; off > 0; off >>= 1)
            mx = fmaxf(mx, __shfl_xor_sync(0xffffffffu, mx, off));
        if (lane == 0) red[wid * 12 + h] = mx;
    }
    __syncthreads();
    float mxh[12];
#pragma unroll
    for (int h = 0; h < 12; h++) {
        float m = red[h];
#pragma unroll
        for (int w = 1; w < 8; w++) m = fmaxf(m, red[w * 12 + h]);
        mxh[h] = m;
    }
    __syncthreads();

#pragma unroll
    for (int h = 0; h < 12; h++) {
        float s = 0.f;
#pragma unroll
        for (int u = 0; u < 3; u++) {
            float e = __expf(acc[h][u] - mxh[h]);
            acc[h][u] = e;
            s += e;
        }
#pragma unroll
        for (int off = 16; off > 0; off >>= 1)
            s += __shfl_xor_sync(0xffffffffu, s, off);
        if (lane == 0) red[wid * 12 + h] = s;
    }
    __syncthreads();
    float smh[12];
#pragma unroll
    for (int h = 0; h < 12; h++) {
        float s = 0.f;
#pragma unroll
        for (int w = 0; w < 8; w++) s += red[w * 12 + h];
        smh[h] = 1.f / s;
    }

    // store attn: padded [j][16] layout (h<6 -> h, h>=6 -> h+2)
#pragma unroll
    for (int h = 0; h < 12; h++) {
        const int off = (h < 6) ? h : h + 2;
        float* arow = d_attn + ((size_t)i * Hh + h) * Nn;
#pragma unroll
        for (int u = 0; u < 3; u++) {
            float a = acc[h][u] * smh[h];
            int j = tid + 256 * u;
            arow[j] = a;
            att_s[j * 16 + off] = a;
        }
    }
    __syncthreads();

    // ---- phase C: r2d; cp.async 16-j chunks, TRIPLE buffer, one barrier per chunk ----
    {
        const int c4 = tid & 31;
        const int hh = (tid >> 5) & 1;
        const int js = tid >> 6;                     // 0..3, 4 j each per chunk
        const unsigned stC = smem_u32(sm + 12288);   // 3 buffers of 2048 floats
        float r2[24] = {};

        // prologue: chunk 0 -> slot 0
#pragma unroll
        for (int t = 0; t < 2; t++) {
            int k = tid + 256 * t;
            int jl = k >> 5, c4i = k & 31;
            const float4* src = in4 + (size_t)jl * 32 + c4i;
            asm volatile("cp.async.cg.shared.global [%0], [%1], 16;"
                         :: "r"(stC + (unsigned)k * 16), "l"(src));
        }
        asm volatile("cp.async.commit_group;");

        const float4* a4 = (const float4*)att_s;
        for (int ch = 0; ch < 48; ch++) {
            const int slot = ch % 3;
            if (ch + 1 < 48) {
                const int ns = (ch + 1) % 3;
                const unsigned dst0 = stC + (unsigned)(ns * 2048) * 4u;
#pragma unroll
                for (int t = 0; t < 2; t++) {
                    int k = tid + 256 * t;
                    int jl = k >> 5, c4i = k & 31;
                    const float4* src = in4 + (size_t)((ch + 1) * 16 + jl) * 32 + c4i;
                    asm volatile("cp.async.cg.shared.global [%0], [%1], 16;"
                                 :: "r"(dst0 + (unsigned)k * 16), "l"(src));
                }
                asm volatile("cp.async.commit_group;");
                asm volatile("cp.async.wait_group 1;");
            } else {
                asm volatile("cp.async.wait_group 0;");
            }
            __syncthreads();
            const float4* xb = (const float4*)(sm + 12288 + slot * 2048);
            const int jb = js * 4;
#pragma unroll
            for (int s = 0; s < 4; s++) {
                const int jl = jb + s;
                float4 x = xb[jl * 32 + c4];
                const int j = ch * 16 + jl;
                float4 aA = a4[j * 4 + hh * 2];
                float4 aB = a4[j * 4 + hh * 2 + 1];
                r2[0]  += aA.x * x.x; r2[1]  += aA.x * x.y; r2[2]  += aA.x * x.z; r2[3]  += aA.x * x.w;
                r2[4]  += aA.y * x.x; r2[5]  += aA.y * x.y; r2[6]  += aA.y * x.z; r2[7]  += aA.y * x.w;
                r2[8]  += aA.z * x.x; r2[9]  += aA.z * x.y; r2[10] += aA.z * x.z; r2[11] += aA.z * x.w;
                r2[12] += aA.w * x.x; r2[13] += aA.w * x.y; r2[14] += aA.w * x.z; r2[15] += aA.w * x.w;
                r2[16] += aB.x * x.x; r2[17] += aB.x * x.y; r2[18] += aB.x * x.z; r2[19] += aB.x * x.w;
                r2[20] += aB.y * x.x; r2[21] += aB.y * x.y; r2[22] += aB.y * x.z; r2[23] += aB.y * x.w;
            }
            // no trailing barrier: next overwrite of this slot is 3 chunks away,
            // separated by the barrier of the next iteration
        }
        __syncthreads();  // all reads of att_s done before redc aliases it

        float* redc = sm;  // 6144 floats
#pragma unroll
        for (int e = 0; e < 6; e++) {
            float4 v = make_float4(r2[e * 4 + 0], r2[e * 4 + 1], r2[e * 4 + 2], r2[e * 4 + 3]);
            *(float4*)&redc[js * 1536 + (hh * 6 + e) * 128 + c4 * 4] = v;
        }
        __syncthreads();
        float* fa = d_fa + (size_t)i * FA_DIM + 576;
        for (int k = tid; k < 1536; k += 256)
            fa[k] = redc[k] + redc[1536 + k] + redc[3072 + k] + redc[4608 + k];
    }
}

// ---------------- K5: PV tiled GEMM, cp.async double buffer ----------------
__global__ __launch_bounds__(256) void pv_kernel() {
    __shared__ float att_s[2][64 * 33];
    __shared__ float v_s[2][32 * 40];
    const int i0 = blockIdx.x * 64;
    const int h = blockIdx.y;
    const int tid = threadIdx.x;
    const int io2 = tid & 31, ov = tid >> 5;
    const unsigned ab = smem_u32(&att_s[0][0]);
    const unsigned vb = smem_u32(&v_s[0][0]);
    float acc0[5] = {}, acc1[5] = {};

    auto issue = [&](int buf, int jt) {
#pragma unroll
        for (int k = 0; k < 8; k++) {
            int f = tid + 256 * k;
            int il = f >> 5, jl = f & 31;
            cp4(ab + (unsigned)(buf * 2112 + il * 33 + jl) * 4u,
                d_attn + ((size_t)(i0 + il) * 12 + h) * Nn + jt + jl);
        }
#pragma unroll
        for (int k = 0; k < 5; k++) {
            int f = tid + 256 * k;
            int jl = f / 40, o = f % 40;
            const float* vr = d_vcat + (size_t)(jt + jl) * 480;
            const float* src = (o < 16) ? (vr + h * 16 + o) : (vr + 192 + h * 24 + (o - 16));
            cp4(vb + (unsigned)(buf * 1280 + jl * 40 + o) * 4u, src);
        }
        asm volatile("cp.async.commit_group;");
    };

    issue(0, 0);
    for (int c = 0; c < 24; c++) {
        const int buf = c & 1;
        if (c + 1 < 24) {
            issue(buf ^ 1, (c + 1) * 32);
            asm volatile("cp.async.wait_group 1;");
        } else {
            asm volatile("cp.async.wait_group 0;");
        }
        __syncthreads();
#pragma unroll 4
        for (int jl = 0; jl < 32; jl++) {
            float a0 = att_s[buf][io2 * 33 + jl];
            float a1 = att_s[buf][(io2 + 32) * 33 + jl];
#pragma unroll
            for (int u = 0; u < 5; u++) {
                float vv = v_s[buf][jl * 40 + ov * 5 + u];
                acc0[u] += a0 * vv;
                acc1[u] += a1 * vv;
            }
        }
        __syncthreads();
    }
#pragma unroll
    for (int u = 0; u < 5; u++) {
        int o = ov * 5 + u;
        int i_a = i0 + io2, i_b = i0 + io2 + 32;
        if (o < 16) {
            d_fa[(size_t)i_a * FA_DIM + h * 16 + o] = acc0[u];
            d_fa[(size_t)i_b * FA_DIM + h * 16 + o] = acc1[u];
        } else {
            d_rpg[i_a * 288 + h * 24 + (o - 16)] = acc0[u];
            d_rpg[i_b * 288 + h * 24 + (o - 16)] = acc1[u];
        }
    }
}

// ---------------- K6: local frame + dist ----------------
__global__ void local_kernel(const float* __restrict__ rot, const float* __restrict__ trans) {
    __shared__ float rpg_s[288], loc[288], Ri[9], ti[3];
    const int i = blockIdx.x;
    const int tid = threadIdx.x;  // 288
    rpg_s[tid] = d_rpg[i * 288 + tid];
    if (tid < 9) Ri[tid] = rot[i * 9 + tid];
    if (tid < 3) ti[tid] = trans[i * 3 + tid];
    __syncthreads();
    float* fa = d_fa + (size_t)i * FA_DIM;
    const int idim = tid / 96, m = tid % 96;
    const int hh = m >> 3, p = m & 7;
    const int base = hh * 24 + p * 3;
    float v0 = rpg_s[base + 0] - ti[0];
    float v1 = rpg_s[base + 1] - ti[1];
    float v2 = rpg_s[base + 2] - ti[2];
    float l = Ri[idim] * v0 + Ri[3 + idim] * v1 + Ri[6 + idim] * v2;
    loc[idim * 96 + m] = l;
    fa[192 + idim * 96 + m] = l;
    __syncthreads();
    if (tid < 96) {
        float l0 = loc[tid], l1 = loc[96 + tid], l2 = loc[192 + tid];
        fa[480 + tid] = sqrtf(1e-8f + l0 * l0 + l1 * l1 + l2 * l2);
    }
}

// ---------------- K7: reduce out partials + bias ----------------
__global__ void reduce_out_kernel(const float* __restrict__ b_out, float* __restrict__ out) {
    const int idx = blockIdx.x * 256 + threadIdx.x;
    const int total = Nn * 384;
    if (idx < total) {
        out[idx] = b_out[idx % 384] + d_part[idx] + d_part[total + idx]
                 + d_part[2 * total + idx] + d_part[3 * total + idx];
    }
}

// ---------------- launch ----------------
extern "C" void kernel_launch(void* const* d_in, const int* in_sizes, int n_in,
                              void* d_out, int out_size) {
    const float* inputs_1d = (const float*)d_in[0];
    const float* inputs_2d = (const float*)d_in[1];
    const float* mask      = (const float*)d_in[2];
    const float* rotation  = (const float*)d_in[3];
    const float* translat  = (const float*)d_in[4];
    const float* w_qs      = (const float*)d_in[5];
    const float* b_qs      = (const float*)d_in[6];
    const float* w_kvs     = (const float*)d_in[7];
    const float* b_kvs     = (const float*)d_in[8];
    const float* w_qp      = (const float*)d_in[9];
    const float* b_qp      = (const float*)d_in[10];
    const float* w_kvp     = (const float*)d_in[11];
    const float* b_kvp     = (const float*)d_in[12];
    const float* tpw       = (const float*)d_in[13];
    const float* w_a2      = (const float*)d_in[14];
    const float* b_a2      = (const float*)d_in[15];
    const float* w_out     = (const float*)d_in[16];
    const float* b_out     = (const float*)d_in[17];
    float* out = (float*)d_out;

    gemm_proj_kernel<<<dim3(PROJ_DIM / 64, Nn / 64), 256>>>(
        inputs_1d, w_qs, w_kvs, w_qp, w_kvp, b_qs, b_kvs, b_qp, b_kvp);

    rot_kernel<<<Nn, 192>>>(rotation, translat, tpw, b_a2);

    lgsp_kernel<<<dim3(6, 12, 12), 128>>>(mask);

    {
        const int smem = 18432 * (int)sizeof(float);  // 73728 B
        cudaFuncSetAttribute(attn_fused_kernel, cudaFuncAttributeMaxDynamicSharedMemorySize, smem);
        attn_fused_kernel<<<Nn, 256, smem>>>(inputs_2d, w_a2);
    }

    pv_kernel<<<dim3(Nn / 64, Hh), 256>>>();
    local_kernel<<<Nn, 288>>>(rotation, translat);

    gemm_out_kernel<<<dim3(384 / 64, Nn / 64, 4), 256>>>(w_out);
    reduce_out_kernel<<<(Nn * 384 + 255) / 256, 256>>>(b_out, out);
}

// round 17
// speedup vs baseline: 1.0495x; 1.0495x over previous
#include <cuda_runtime.h>
#include <math.h>
#include <stdint.h>

#define Hh   12
#define Nn   768
#define C1d  384
#define C2d  128
#define PROJ_DIM 1152
#define FA_DIM   2112

#define SCALAR_W 0.14433756729740643f
#define POINT_W  0.13608276348795434f
#define W2D      0.5773502691896258f

// ---------------- scratch ----------------
__device__ float d_proj[Nn * PROJ_DIM];
__device__ float d_qcat[Nn * 384];
__device__ float d_kT[Hh * 29 * Nn];
__device__ float d_vcat[Nn * 480];
__device__ float d_lgsp[Nn * Hh * Nn];
__device__ float d_attn[Hh * Nn * Nn];
__device__ float d_rpg[Nn * 288];
__device__ float d_fa[Nn * FA_DIM];
__device__ float d_part[4 * Nn * 384];

__device__ __forceinline__ unsigned smem_u32(const void* p) {
    unsigned a;
    asm("{ .reg .u64 t; cvta.to.shared.u64 t, %1; cvt.u32.u64 %0, t; }" : "=r"(a) : "l"(p));
    return a;
}
__device__ __forceinline__ void cp4(unsigned dst, const float* src) {
    asm volatile("cp.async.ca.shared.global [%0], [%1], 4;" :: "r"(dst), "l"(src));
}

// ---------------- K1: proj GEMM fp32, cp.async double buffer, inline weight concat ----------------
__global__ __launch_bounds__(256) void gemm_proj_kernel(
        const float* __restrict__ X,
        const float* __restrict__ wqs, const float* __restrict__ wkvs,
        const float* __restrict__ wqp, const float* __restrict__ wkvp,
        const float* __restrict__ bqs, const float* __restrict__ bkvs,
        const float* __restrict__ bqp, const float* __restrict__ bkvp) {
    __shared__ float xsT[2][16][68];
    __shared__ float wsT[2][16][68];
    const int m0 = blockIdx.y * 64, o0 = blockIdx.x * 64;
    const int tx = threadIdx.x;
    const int tm = (tx & 15) * 4;
    const int to = (tx >> 4) * 4;
    const unsigned xb = smem_u32(&xsT[0][0][0]);
    const unsigned wb = smem_u32(&wsT[0][0][0]);
    float acc[4][4] = {};

    auto issue = [&](int buf, int k0) {
#pragma unroll
        for (int t = 0; t < 4; t++) {
            int idx = tx + 256 * t;
            int r = idx >> 4, c = idx & 15;
            cp4(xb + (unsigned)(buf * 1088 + c * 68 + r) * 4u,
                X + (size_t)(m0 + r) * C1d + k0 + c);
            int o = o0 + r;
            const float* wrow;
            if (o < 192)      wrow = wqs  + (size_t)o * C1d;
            else if (o < 576) wrow = wkvs + (size_t)(o - 192) * C1d;
            else if (o < 720) wrow = wqp  + (size_t)(o - 576) * C1d;
            else              wrow = wkvp + (size_t)(o - 720) * C1d;
            cp4(wb + (unsigned)(buf * 1088 + c * 68 + r) * 4u, wrow + k0 + c);
        }
        asm volatile("cp.async.commit_group;");
    };

    issue(0, 0);
    const int NK = C1d / 16;
    for (int kk = 0; kk < NK; kk++) {
        const int buf = kk & 1;
        if (kk + 1 < NK) {
            issue(buf ^ 1, (kk + 1) * 16);
            asm volatile("cp.async.wait_group 1;");
        } else {
            asm volatile("cp.async.wait_group 0;");
        }
        __syncthreads();
#pragma unroll
        for (int k = 0; k < 16; k++) {
            float4 av = *(const float4*)&xsT[buf][k][tm];
            float4 bv = *(const float4*)&wsT[buf][k][to];
            float a[4] = {av.x, av.y, av.z, av.w};
            float b[4] = {bv.x, bv.y, bv.z, bv.w};
#pragma unroll
            for (int i = 0; i < 4; i++)
#pragma unroll
                for (int j = 0; j < 4; j++) acc[i][j] += a[i] * b[j];
        }
        __syncthreads();
    }
#pragma unroll
    for (int i = 0; i < 4; i++)
#pragma unroll
        for (int j = 0; j < 4; j++) {
            int o = o0 + to + j;
            float bv;
            if (o < 192)      bv = bqs[o];
            else if (o < 576) bv = bkvs[o - 192];
            else if (o < 720) bv = bqp[o - 576];
            else              bv = bkvp[o - 720];
            d_proj[(size_t)(m0 + tm + i) * PROJ_DIM + o] = acc[i][j] + bv;
        }
}

// ---------------- out-GEMM fp32, cp.async double buffer, K-split on blockIdx.z ----------------
__global__ __launch_bounds__(256) void gemm_out_kernel(const float* __restrict__ Wo) {
    __shared__ float xsT[2][16][68];
    __shared__ float wsT[2][16][68];
    const int z  = blockIdx.z;
    const float* X = d_fa + z * 528;
    const float* W = Wo + z * 528;
    float* C = d_part + (size_t)z * (Nn * 384);
    const int m0 = blockIdx.y * 64, o0 = blockIdx.x * 64;
    const int tx = threadIdx.x;
    const int tm = (tx & 15) * 4;
    const int to = (tx >> 4) * 4;
    const unsigned xb = smem_u32(&xsT[0][0][0]);
    const unsigned wb = smem_u32(&wsT[0][0][0]);
    float acc[4][4] = {};

    auto issue = [&](int buf, int k0) {
#pragma unroll
        for (int t = 0; t < 4; t++) {
            int idx = tx + 256 * t;
            int r = idx >> 4, c = idx & 15;
            cp4(xb + (unsigned)(buf * 1088 + c * 68 + r) * 4u,
                X + (size_t)(m0 + r) * FA_DIM + k0 + c);
            cp4(wb + (unsigned)(buf * 1088 + c * 68 + r) * 4u,
                W + (size_t)(o0 + r) * FA_DIM + k0 + c);
        }
        asm volatile("cp.async.commit_group;");
    };

    issue(0, 0);
    const int NK = 528 / 16;
    for (int kk = 0; kk < NK; kk++) {
        const int buf = kk & 1;
        if (kk + 1 < NK) {
            issue(buf ^ 1, (kk + 1) * 16);
            asm volatile("cp.async.wait_group 1;");
        } else {
            asm volatile("cp.async.wait_group 0;");
        }
        __syncthreads();
#pragma unroll
        for (int k = 0; k < 16; k++) {
            float4 av = *(const float4*)&xsT[buf][k][tm];
            float4 bv = *(const float4*)&wsT[buf][k][to];
            float a[4] = {av.x, av.y, av.z, av.w};
            float b[4] = {bv.x, bv.y, bv.z, bv.w};
#pragma unroll
            for (int i = 0; i < 4; i++)
#pragma unroll
                for (int j = 0; j < 4; j++) acc[i][j] += a[i] * b[j];
        }
        __syncthreads();
    }
#pragma unroll
    for (int i = 0; i < 4; i++)
#pragma unroll
        for (int j = 0; j < 4; j++)
            C[(size_t)(m0 + tm + i) * 384 + o0 + to + j] = acc[i][j];
}

// ---------------- K2: rotations / frames / norms / packed q ----------------
__global__ void rot_kernel(const float* __restrict__ rot, const float* __restrict__ trans,
                           const float* __restrict__ tpw, const float* __restrict__ b_a2) {
    const int n = blockIdx.x;
    const int tid = threadIdx.x;  // 192
    __shared__ float R[9], t3[3], qn_s[Hh], kn_s[Hh], pwb_s[Hh];
    const float* pr = d_proj + (size_t)n * PROJ_DIM;
    if (tid < 9)  R[tid] = rot[n * 9 + tid];
    if (tid < 3)  t3[tid] = trans[n * 3 + tid];
    if (tid < Hh) {
        qn_s[tid] = 0.f; kn_s[tid] = 0.f;
        float x = tpw[tid];
        float sp = (x > 20.f) ? x : log1pf(__expf(x));
        pwb_s[tid] = -0.5f * sp * POINT_W;
    }
    __syncthreads();

    { int h = tid >> 4, f = tid & 15;
      d_qcat[n * 384 + h * 32 + f] = SCALAR_W * pr[tid]; }
    for (int o = tid; o < 384; o += 192) {
        int h = o >> 5, d = o & 31;
        float v = pr[192 + o];
        if (d < 16) d_kT[(size_t)(h * 29 + d) * Nn + n] = v;
        else        d_vcat[(size_t)n * 480 + h * 16 + (d - 16)] = v;
    }
    if (tid < 48) {
        int m = tid;
        float p0 = pr[576 + 0 * 48 + m];
        float p1 = pr[576 + 1 * 48 + m];
        float p2 = pr[576 + 2 * 48 + m];
        float g0 = R[0] * p0 + R[1] * p1 + R[2] * p2 + t3[0];
        float g1 = R[3] * p0 + R[4] * p1 + R[5] * p2 + t3[1];
        float g2 = R[6] * p0 + R[7] * p1 + R[8] * p2 + t3[2];
        int h = m >> 2, p = m & 3;
        float s = -2.f * pwb_s[h];
        int base = n * 384 + h * 32 + 16 + p * 3;
        d_qcat[base + 0] = s * g0; d_qcat[base + 1] = s * g1; d_qcat[base + 2] = s * g2;
        atomicAdd(&qn_s[h], g0 * g0 + g1 * g1 + g2 * g2);
    } else {
        int m = tid - 48;
        float p0 = pr[720 + 0 * 144 + m];
        float p1 = pr[720 + 1 * 144 + m];
        float p2 = pr[720 + 2 * 144 + m];
        float g0 = R[0] * p0 + R[1] * p1 + R[2] * p2 + t3[0];
        float g1 = R[3] * p0 + R[4] * p1 + R[5] * p2 + t3[1];
        float g2 = R[6] * p0 + R[7] * p1 + R[8] * p2 + t3[2];
        int h = m / 12, pp = m % 12;
        if (pp < 4) {
            int fb = h * 29 + 16 + pp * 3;
            d_kT[(size_t)(fb + 0) * Nn + n] = g0;
            d_kT[(size_t)(fb + 1) * Nn + n] = g1;
            d_kT[(size_t)(fb + 2) * Nn + n] = g2;
            atomicAdd(&kn_s[h], g0 * g0 + g1 * g1 + g2 * g2);
        } else {
            int base = n * 480 + 192 + h * 24 + (pp - 4) * 3;
            d_vcat[base + 0] = g0; d_vcat[base + 1] = g1; d_vcat[base + 2] = g2;
        }
    }
    __syncthreads();
    if (tid < Hh) {
        int qb = n * 384 + tid * 32;
        d_qcat[qb + 28] = pwb_s[tid];
        d_qcat[qb + 29] = pwb_s[tid] * qn_s[tid] + W2D * b_a2[tid];
        d_qcat[qb + 30] = 0.f;
        d_qcat[qb + 31] = 0.f;
        d_kT[(size_t)(tid * 29 + 28) * Nn + n] = kn_s[tid];
    }
}

// ---------------- K3: scalar/point logits, K=29 GEMM, 8x8 register tile ----------------
__global__ __launch_bounds__(128) void lgsp_kernel(const float* __restrict__ mask) {
    __shared__ float q_s[64][36];
    __shared__ float kt_s[29][132];
    __shared__ float mj_s[128];
    const int jt = blockIdx.x * 128;
    const int it = blockIdx.y * 64;
    const int h  = blockIdx.z;
    const int tid = threadIdx.x;

    for (int k = tid; k < 512; k += 128) {
        int r = k >> 3, c4 = k & 7;
        *(((float4*)&q_s[r][0]) + c4) =
            *(((const float4*)(d_qcat + (size_t)(it + r) * 384 + h * 32)) + c4);
    }
    for (int k = tid; k < 928; k += 128) {
        int f = k >> 5, c4 = k & 31;
        *(((float4*)&kt_s[f][0]) + c4) =
            *(((const float4*)(d_kT + (size_t)(h * 29 + f) * Nn + jt)) + c4);
    }
    if (tid < 128) mj_s[tid] = mask[jt + tid];
    __syncthreads();

    const int tj = tid & 15, ti = tid >> 4;
    float acc[8][8] = {};
#pragma unroll
    for (int f = 0; f < 29; f++) {
        float a[8];
        float4 b0 = *((const float4*)&kt_s[f][tj * 8]);
        float4 b1 = *((const float4*)&kt_s[f][tj * 8 + 4]);
        float b[8] = {b0.x, b0.y, b0.z, b0.w, b1.x, b1.y, b1.z, b1.w};
#pragma unroll
        for (int r = 0; r < 8; r++) a[r] = q_s[ti * 8 + r][f];
#pragma unroll
        for (int r = 0; r < 8; r++)
#pragma unroll
            for (int c = 0; c < 8; c++) acc[r][c] += a[r] * b[c];
    }
#pragma unroll
    for (int r = 0; r < 8; r++) {
        const int ii = it + ti * 8 + r;
        const float mi = mask[ii];
        const float cih = q_s[ti * 8 + r][29];
        float4* orow = (float4*)(d_lgsp + ((size_t)ii * Hh + h) * Nn + jt + tj * 8);
        float4 o0, o1;
        o0.x = acc[r][0] + cih - 100000.f * (1.f - mi * mj_s[tj * 8 + 0]);
        o0.y = acc[r][1] + cih - 100000.f * (1.f - mi * mj_s[tj * 8 + 1]);
        o0.z = acc[r][2] + cih - 100000.f * (1.f - mi * mj_s[tj * 8 + 2]);
        o0.w = acc[r][3] + cih - 100000.f * (1.f - mi * mj_s[tj * 8 + 3]);
        o1.x = acc[r][4] + cih - 100000.f * (1.f - mi * mj_s[tj * 8 + 4]);
        o1.y = acc[r][5] + cih - 100000.f * (1.f - mi * mj_s[tj * 8 + 5]);
        o1.z = acc[r][6] + cih - 100000.f * (1.f - mi * mj_s[tj * 8 + 6]);
        o1.w = acc[r][7] + cih - 100000.f * (1.f - mi * mj_s[tj * 8 + 7]);
        orow[0] = o0; orow[1] = o1;
    }
}

// ---------------- K4: fused attn — cp.async pipelined phase A AND phase C (round-14 config) ----------------
// 768 blocks, 256 threads, dyn smem 69632 B, 3 blocks/SM
// smem floats (aliased by phase):
//   A: stageA [0,12288)  ws4 [12288,13872)  red [13872,13968)
//   B: att_s [0,9216)    red [13872,13968)
//   C: att_s [0,9216)    bufC0 [9216,13312)  bufC1 [13312,17408); redc [9216,15360) after
__global__ void __launch_bounds__(256, 3) attn_fused_kernel(const float* __restrict__ in2d,
                                                            const float* __restrict__ w_a2) {
    extern __shared__ float sm[];
    float4* ws4 = (float4*)(sm + 12288);
    float* red  = sm + 13872;
    float* att_s = sm;

    const int i = blockIdx.x;
    const int tid = threadIdx.x;
    const int wid = tid >> 5, lane = tid & 31;

    const float4* w4g = (const float4*)w_a2;
    for (int k = tid; k < 384; k += 256)
        ws4[(k >> 5) * 33 + (k & 31)] = w4g[k];

    const float4* in4 = (const float4*)in2d + (size_t)i * Nn * 32;
    const unsigned stage_base = smem_u32(sm);

    // ---- phase A: a2d GEMM, 16 chunks of 8 cols, cp.async double buffer ----
    float acc[12][3] = {};
    {
#pragma unroll
        for (int t = 0; t < 6; t++) {
            int k = tid + 256 * t;
            int j = k >> 1, c2 = k & 1;
            const float4* src = in4 + (size_t)j * 32 + c2;
            asm volatile("cp.async.cg.shared.global [%0], [%1], 16;"
                         :: "r"(stage_base + (unsigned)k * 16), "l"(src));
        }
        asm volatile("cp.async.commit_group;");

        for (int ch = 0; ch < 16; ch++) {
            const int buf = ch & 1;
            if (ch + 1 < 16) {
                const unsigned dst0 = stage_base + (unsigned)((buf ^ 1) * 6144) * 4u;
#pragma unroll
                for (int t = 0; t < 6; t++) {
                    int k = tid + 256 * t;
                    int j = k >> 1, c2 = k & 1;
                    const float4* src = in4 + (size_t)j * 32 + (ch + 1) * 2 + c2;
                    asm volatile("cp.async.cg.shared.global [%0], [%1], 16;"
                                 :: "r"(dst0 + (unsigned)k * 16), "l"(src));
                }
                asm volatile("cp.async.commit_group;");
                asm volatile("cp.async.wait_group 1;");
            } else {
                asm volatile("cp.async.wait_group 0;");
            }
            __syncthreads();
            const float4* xsb = (const float4*)(sm + buf * 6144);
#pragma unroll
            for (int c4 = 0; c4 < 2; c4++) {
                float4 xv[3];
#pragma unroll
                for (int u = 0; u < 3; u++) xv[u] = xsb[(tid + 256 * u) * 2 + c4];
#pragma unroll
                for (int h = 0; h < 12; h++) {
                    float4 wv = ws4[h * 33 + ch * 2 + c4];
#pragma unroll
                    for (int u = 0; u < 3; u++)
                        acc[h][u] += xv[u].x * wv.x + xv[u].y * wv.y
                                   + xv[u].z * wv.z + xv[u].w * wv.w;
                }
            }
            __syncthreads();
        }
    }

    // ---- phase B: + lgsp, softmax (register-resident) ----
    const float* lgp = d_lgsp + (size_t)i * Hh * Nn;
#pragma unroll
    for (int h = 0; h < 12; h++) {
        float mx = -1e30f;
#pragma unroll
        for (int u = 0; u < 3; u++) {
            float L = acc[h][u] * W2D + lgp[h * Nn + tid + 256 * u];
            acc[h][u] = L;
            mx = fmaxf(mx, L);
        }
#pragma unroll
        for (int off = 16; off > 0; off >>= 1)
            mx = fmaxf(mx, __shfl_xor_sync(0xffffffffu, mx, off));
        if (lane == 0) red[wid * 12 + h] = mx;
    }
    __syncthreads();
    float mxh[12];
#pragma unroll
    for (int h = 0; h < 12; h++) {
        float m = red[h];
#pragma unroll
        for (int w = 1; w < 8; w++) m = fmaxf(m, red[w * 12 + h]);
        mxh[h] = m;
    }
    __syncthreads();

#pragma unroll
    for (int h = 0; h < 12; h++) {
        float s = 0.f;
#pragma unroll
        for (int u = 0; u < 3; u++) {
            float e = __expf(acc[h][u] - mxh[h]);
            acc[h][u] = e;
            s += e;
        }
#pragma unroll
        for (int off = 16; off > 0; off >>= 1)
            s += __shfl_xor_sync(0xffffffffu, s, off);
        if (lane == 0) red[wid * 12 + h] = s;
    }
    __syncthreads();
    float smh[12];
#pragma unroll
    for (int h = 0; h < 12; h++) {
        float s = 0.f;
#pragma unroll
        for (int w = 0; w < 8; w++) s += red[w * 12 + h];
        smh[h] = 1.f / s;
    }

#pragma unroll
    for (int h = 0; h < 12; h++) {
        float* arow = d_attn + ((size_t)i * Hh + h) * Nn;
#pragma unroll
        for (int u = 0; u < 3; u++) {
            float a = acc[h][u] * smh[h];
            int j = tid + 256 * u;
            arow[j] = a;
            att_s[j * 12 + h] = a;
        }
    }
    __syncthreads();

    // ---- phase C: r2d = attn[12,768] @ X[768,128]; cp.async row-chunks of 32 j ----
    {
        const int c4 = tid & 31;
        const int hh = (tid >> 5) & 1;
        const int js = tid >> 6;                  // 0..3, 8 j each per chunk
        const unsigned stC = smem_u32(sm + 9216); // 2 buffers of 4096 floats
        float r2[24] = {};

        // issue chunk 0 -> bufC0
#pragma unroll
        for (int t = 0; t < 4; t++) {
            int k = tid + 256 * t;            // 0..1023 f4 units
            int jl = k >> 5, c4i = k & 31;
            const float4* src = in4 + (size_t)jl * 32 + c4i;
            asm volatile("cp.async.cg.shared.global [%0], [%1], 16;"
                         :: "r"(stC + (unsigned)k * 16), "l"(src));
        }
        asm volatile("cp.async.commit_group;");

        for (int ch = 0; ch < 24; ch++) {
            const int buf = ch & 1;
            if (ch + 1 < 24) {
                const unsigned dst0 = stC + (unsigned)((buf ^ 1) * 4096) * 4u;
#pragma unroll
                for (int t = 0; t < 4; t++) {
                    int k = tid + 256 * t;
                    int jl = k >> 5, c4i = k & 31;
                    const float4* src = in4 + (size_t)((ch + 1) * 32 + jl) * 32 + c4i;
                    asm volatile("cp.async.cg.shared.global [%0], [%1], 16;"
                                 :: "r"(dst0 + (unsigned)k * 16), "l"(src));
                }
                asm volatile("cp.async.commit_group;");
                asm volatile("cp.async.wait_group 1;");
            } else {
                asm volatile("cp.async.wait_group 0;");
            }
            __syncthreads();
            const float4* xb = (const float4*)(sm + 9216 + buf * 4096);
            const int jb = js * 8;
#pragma unroll
            for (int s = 0; s < 8; s++) {
                int jl = jb + s;
                float4 x = xb[jl * 32 + c4];
                const float* a = att_s + (ch * 32 + jl) * 12 + hh * 6;
#pragma unroll
                for (int e = 0; e < 6; e++) {
                    float av = a[e];
                    r2[e * 4 + 0] += av * x.x;
                    r2[e * 4 + 1] += av * x.y;
                    r2[e * 4 + 2] += av * x.z;
                    r2[e * 4 + 3] += av * x.w;
                }
            }
            __syncthreads();
        }

        // reduce 4-way over js into aliased stage region
        float* redc = sm + 9216;  // 6144 floats
#pragma unroll
        for (int e = 0; e < 6; e++) {
            float4 v = make_float4(r2[e * 4 + 0], r2[e * 4 + 1], r2[e * 4 + 2], r2[e * 4 + 3]);
            *(float4*)&redc[js * 1536 + (hh * 6 + e) * 128 + c4 * 4] = v;
        }
        __syncthreads();
        float* fa = d_fa + (size_t)i * FA_DIM + 576;
        for (int k = tid; k < 1536; k += 256)
            fa[k] = redc[k] + redc[1536 + k] + redc[3072 + k] + redc[4608 + k];
    }
}

// ---------------- K5: PV tiled GEMM, cp.async double buffer ----------------
__global__ __launch_bounds__(256) void pv_kernel() {
    __shared__ float att_s[2][64 * 33];
    __shared__ float v_s[2][32 * 40];
    const int i0 = blockIdx.x * 64;
    const int h = blockIdx.y;
    const int tid = threadIdx.x;
    const int io2 = tid & 31, ov = tid >> 5;
    const unsigned ab = smem_u32(&att_s[0][0]);
    const unsigned vb = smem_u32(&v_s[0][0]);
    float acc0[5] = {}, acc1[5] = {};

    auto issue = [&](int buf, int jt) {
#pragma unroll
        for (int k = 0; k < 8; k++) {
            int f = tid + 256 * k;
            int il = f >> 5, jl = f & 31;
            cp4(ab + (unsigned)(buf * 2112 + il * 33 + jl) * 4u,
                d_attn + ((size_t)(i0 + il) * 12 + h) * Nn + jt + jl);
        }
#pragma unroll
        for (int k = 0; k < 5; k++) {
            int f = tid + 256 * k;
            int jl = f / 40, o = f % 40;
            const float* vr = d_vcat + (size_t)(jt + jl) * 480;
            const float* src = (o < 16) ? (vr + h * 16 + o) : (vr + 192 + h * 24 + (o - 16));
            cp4(vb + (unsigned)(buf * 1280 + jl * 40 + o) * 4u, src);
        }
        asm volatile("cp.async.commit_group;");
    };

    issue(0, 0);
    for (int c = 0; c < 24; c++) {
        const int buf = c & 1;
        if (c + 1 < 24) {
            issue(buf ^ 1, (c + 1) * 32);
            asm volatile("cp.async.wait_group 1;");
        } else {
            asm volatile("cp.async.wait_group 0;");
        }
        __syncthreads();
#pragma unroll 4
        for (int jl = 0; jl < 32; jl++) {
            float a0 = att_s[buf][io2 * 33 + jl];
            float a1 = att_s[buf][(io2 + 32) * 33 + jl];
#pragma unroll
            for (int u = 0; u < 5; u++) {
                float vv = v_s[buf][jl * 40 + ov * 5 + u];
                acc0[u] += a0 * vv;
                acc1[u] += a1 * vv;
            }
        }
        __syncthreads();
    }
#pragma unroll
    for (int u = 0; u < 5; u++) {
        int o = ov * 5 + u;
        int i_a = i0 + io2, i_b = i0 + io2 + 32;
        if (o < 16) {
            d_fa[(size_t)i_a * FA_DIM + h * 16 + o] = acc0[u];
            d_fa[(size_t)i_b * FA_DIM + h * 16 + o] = acc1[u];
        } else {
            d_rpg[i_a * 288 + h * 24 + (o - 16)] = acc0[u];
            d_rpg[i_b * 288 + h * 24 + (o - 16)] = acc1[u];
        }
    }
}

// ---------------- K6: local frame + dist ----------------
__global__ void local_kernel(const float* __restrict__ rot, const float* __restrict__ trans) {
    __shared__ float rpg_s[288], loc[288], Ri[9], ti[3];
    const int i = blockIdx.x;
    const int tid = threadIdx.x;  // 288
    rpg_s[tid] = d_rpg[i * 288 + tid];
    if (tid < 9) Ri[tid] = rot[i * 9 + tid];
    if (tid < 3) ti[tid] = trans[i * 3 + tid];
    __syncthreads();
    float* fa = d_fa + (size_t)i * FA_DIM;
    const int idim = tid / 96, m = tid % 96;
    const int hh = m >> 3, p = m & 7;
    const int base = hh * 24 + p * 3;
    float v0 = rpg_s[base + 0] - ti[0];
    float v1 = rpg_s[base + 1] - ti[1];
    float v2 = rpg_s[base + 2] - ti[2];
    float l = Ri[idim] * v0 + Ri[3 + idim] * v1 + Ri[6 + idim] * v2;
    loc[idim * 96 + m] = l;
    fa[192 + idim * 96 + m] = l;
    __syncthreads();
    if (tid < 96) {
        float l0 = loc[tid], l1 = loc[96 + tid], l2 = loc[192 + tid];
        fa[480 + tid] = sqrtf(1e-8f + l0 * l0 + l1 * l1 + l2 * l2);
    }
}

// ---------------- K7: reduce out partials + bias ----------------
__global__ void reduce_out_kernel(const float* __restrict__ b_out, float* __restrict__ out) {
    const int idx = blockIdx.x * 256 + threadIdx.x;
    const int total = Nn * 384;
    if (idx < total) {
        out[idx] = b_out[idx % 384] + d_part[idx] + d_part[total + idx]
                 + d_part[2 * total + idx] + d_part[3 * total + idx];
    }
}

// ---------------- launch ----------------
extern "C" void kernel_launch(void* const* d_in, const int* in_sizes, int n_in,
                              void* d_out, int out_size) {
    const float* inputs_1d = (const float*)d_in[0];
    const float* inputs_2d = (const float*)d_in[1];
    const float* mask      = (const float*)d_in[2];
    const float* rotation  = (const float*)d_in[3];
    const float* translat  = (const float*)d_in[4];
    const float* w_qs      = (const float*)d_in[5];
    const float* b_qs      = (const float*)d_in[6];
    const float* w_kvs     = (const float*)d_in[7];
    const float* b_kvs     = (const float*)d_in[8];
    const float* w_qp      = (const float*)d_in[9];
    const float* b_qp      = (const float*)d_in[10];
    const float* w_kvp     = (const float*)d_in[11];
    const float* b_kvp     = (const float*)d_in[12];
    const float* tpw       = (const float*)d_in[13];
    const float* w_a2      = (const float*)d_in[14];
    const float* b_a2      = (const float*)d_in[15];
    const float* w_out     = (const float*)d_in[16];
    const float* b_out     = (const float*)d_in[17];
    float* out = (float*)d_out;

    gemm_proj_kernel<<<dim3(PROJ_DIM / 64, Nn / 64), 256>>>(
        inputs_1d, w_qs, w_kvs, w_qp, w_kvp, b_qs, b_kvs, b_qp, b_kvp);

    rot_kernel<<<Nn, 192>>>(rotation, translat, tpw, b_a2);

    lgsp_kernel<<<dim3(6, 12, 12), 128>>>(mask);

    {
        const int smem = 17408 * (int)sizeof(float);  // 69632 B
        cudaFuncSetAttribute(attn_fused_kernel, cudaFuncAttributeMaxDynamicSharedMemorySize, smem);
        attn_fused_kernel<<<Nn, 256, smem>>>(inputs_2d, w_a2);
    }

    pv_kernel<<<dim3(Nn / 64, Hh), 256>>>();
    local_kernel<<<Nn, 288>>>(rotation, translat);

    gemm_out_kernel<<<dim3(384 / 64, Nn / 64, 4), 256>>>(w_out);
    reduce_out_kernel<<<(Nn * 384 + 255) / 256, 256>>>(b_out, out);
}